// round 9
// baseline (speedup 1.0000x reference)
#include <cuda_runtime.h>
#include <cuda_bf16.h>
#include <math_constants.h>

#define NN 100000
#define EE 600000

// ---------------- scratch ----------------
__device__ float g_q[NN * 128];
__device__ float g_k[NN * 128];
__device__ float g_v[NN * 128];
__device__ float g_qe[(size_t)NN * 256];    // per-node, per-head We^T q
__device__ float g_accA[(size_t)NN * 256];  // attn-weighted edge_attr sums
__device__ float g_alpha[EE * 2];
__device__ float g_ex[EE * 2];
__device__ float g_amax[NN * 2];
__device__ float g_denom[NN * 2];

__device__ __forceinline__ void atomicMaxF(float* addr, float value) {
    if (value >= 0.f)
        atomicMax((int*)addr, __float_as_int(value));
    else
        atomicMin((unsigned int*)addr, (unsigned int)__float_as_int(value));
}

__device__ __forceinline__ float dot4(float4 a, float4 b) {
    return a.x * b.x + a.y * b.y + a.z * b.z + a.w * b.w;
}

__device__ __forceinline__ void red4(float* p, float4 v) {
    asm volatile("red.global.add.v4.f32 [%0], {%1, %2, %3, %4};"
                 :: "l"(p), "f"(v.x), "f"(v.y), "f"(v.z), "f"(v.w) : "memory");
}

// accurate cos: manual 2pi range reduction + MUFU
__device__ __forceinline__ float cos_fast(float x) {
    float kq = rintf(x * 0.15915494309189535f);
    float r = fmaf(kq, -6.28318548202514648f, x);
    r = fmaf(kq, 1.74845553e-07f, r);
    return __cosf(r);
}

__device__ __forceinline__ void mma16816(float* c, const unsigned* a, const unsigned* b) {
    asm volatile("mma.sync.aligned.m16n8k16.row.col.f32.bf16.bf16.f32 "
        "{%0,%1,%2,%3},{%4,%5,%6,%7},{%8,%9},{%0,%1,%2,%3};"
        : "+f"(c[0]), "+f"(c[1]), "+f"(c[2]), "+f"(c[3])
        : "r"(a[0]), "r"(a[1]), "r"(a[2]), "r"(a[3]), "r"(b[0]), "r"(b[1]));
}

__device__ __forceinline__ void split_bf(float v, unsigned short& h, unsigned short& l) {
    __nv_bfloat16 hb = __float2bfloat16(v);
    __nv_bfloat16 lb = __float2bfloat16(v - __bfloat162float(hb));
    h = __bfloat16_as_ushort(hb);
    l = __bfloat16_as_ushort(lb);
}

// ---------------- kernel 0: init ----------------
__global__ void init_kernel() {
    int i = blockIdx.x * blockDim.x + threadIdx.x;
    if (i < NN * 64) ((float4*)g_accA)[i] = make_float4(0.f, 0.f, 0.f, 0.f);
    if (i < NN * 2) {
        g_amax[i] = -CUDART_INF_F;
        g_denom[i] = 0.f;
    }
}

// ---------------- kernel 1: node projections via bf16-split tensor MMA ----------------
// CTA: 128 rows x 128 cols, K=128. 8 warps: 4 (m) x 2 (n), warp tile 32x64.
// smem: fragment-ordered bf16 planes. A: hi+lo 32KB each; B: hi+lo 32KB each. 128KB.
#define NODE_SMEM (128 * 1024)
__global__ void __launch_bounds__(256, 1)
node_mma_kernel(const float* __restrict__ x,
                const float* __restrict__ Wq, const float* __restrict__ bq,
                const float* __restrict__ Wk, const float* __restrict__ bk,
                const float* __restrict__ Wv, const float* __restrict__ bv,
                const float* __restrict__ Wsk, const float* __restrict__ bsk,
                float* __restrict__ out_skip)
{
    extern __shared__ unsigned smu[];
    unsigned* Ahi = smu;            // 8192 u32
    unsigned* Alo = smu + 8192;
    unsigned* Bhi = smu + 16384;
    unsigned* Blo = smu + 24576;

    const int tid = threadIdx.x;
    const float* W; const float* bias; float* dst;
    switch (blockIdx.y) {
        case 0:  W = Wq;  bias = bq;  dst = g_q;      break;
        case 1:  W = Wk;  bias = bk;  dst = g_k;      break;
        case 2:  W = Wv;  bias = bv;  dst = g_v;      break;
        default: W = Wsk; bias = bsk; dst = out_skip; break;
    }
    const int row0 = blockIdx.x * 128;

    // --- load W [k=128][n=128] into fragment-ordered B planes (STS.16 per element) ---
    #pragma unroll
    for (int i = 0; i < 16; i++) {
        int idx4 = i * 256 + tid;            // 4096 float4
        int k = idx4 >> 5;
        int n0 = (idx4 & 31) * 4;
        float4 v = ((const float4*)W)[idx4];
        float vv[4] = {v.x, v.y, v.z, v.w};
        #pragma unroll
        for (int j = 0; j < 4; j++) {
            int n = n0 + j;
            int lane = ((n & 7) << 2) | ((k & 7) >> 1);
            int reg = (k >> 3) & 1;
            int idx = (((k >> 4) * 16 + (n >> 3)) << 6) + (lane << 1) + reg;
            unsigned short h, l;
            split_bf(vv[j], h, l);
            ((unsigned short*)&Bhi[idx])[k & 1] = h;
            ((unsigned short*)&Blo[idx])[k & 1] = l;
        }
    }

    // --- load x tile [128 rows][k=128] into fragment-ordered A planes ---
    #pragma unroll
    for (int i = 0; i < 16; i++) {
        int idx4 = i * 256 + tid;
        int r = idx4 >> 5;
        int k0 = (idx4 & 31) * 4;
        float4 v = make_float4(0.f, 0.f, 0.f, 0.f);
        if (row0 + r < NN) v = ((const float4*)x)[(size_t)(row0 + r) * 32 + (k0 >> 2)];
        unsigned short h0, l0, h1, l1, h2, l2, h3, l3;
        split_bf(v.x, h0, l0); split_bf(v.y, h1, l1);
        split_bf(v.z, h2, l2); split_bf(v.w, h3, l3);
        int m16 = r >> 4;
        int lane = ((r & 7) << 2) | ((k0 & 7) >> 1);
        int reg = ((r >> 3) & 1) | (((k0 >> 3) & 1) << 1);
        int base = (((k0 >> 4) * 8 + m16) << 7);
        Ahi[base + (lane << 2) + reg]       = (unsigned)h0 | ((unsigned)h1 << 16);
        Alo[base + (lane << 2) + reg]       = (unsigned)l0 | ((unsigned)l1 << 16);
        Ahi[base + ((lane + 1) << 2) + reg] = (unsigned)h2 | ((unsigned)h3 << 16);
        Alo[base + ((lane + 1) << 2) + reg] = (unsigned)l2 | ((unsigned)l3 << 16);
    }
    __syncthreads();

    const int w = tid >> 5, lane = tid & 31;
    const int wm = w & 3, wn = w >> 2;

    float acc[2][8][4];
    #pragma unroll
    for (int mt = 0; mt < 2; mt++)
        #pragma unroll
        for (int nt = 0; nt < 8; nt++)
            #pragma unroll
            for (int j = 0; j < 4; j++) acc[mt][nt][j] = 0.f;

    #pragma unroll
    for (int kk = 0; kk < 8; kk++) {
        unsigned ah[2][4], al[2][4];
        #pragma unroll
        for (int mt = 0; mt < 2; mt++) {
            int m16 = wm * 2 + mt;
            int base = ((kk * 8 + m16) << 7) + (lane << 2);
            *(uint4*)ah[mt] = *(const uint4*)&Ahi[base];
            *(uint4*)al[mt] = *(const uint4*)&Alo[base];
        }
        unsigned bh[8][2], bl[8][2];
        #pragma unroll
        for (int nt = 0; nt < 8; nt++) {
            int n8 = wn * 8 + nt;
            int base = ((kk * 16 + n8) << 6) + (lane << 1);
            *(uint2*)bh[nt] = *(const uint2*)&Bhi[base];
            *(uint2*)bl[nt] = *(const uint2*)&Blo[base];
        }
        #pragma unroll
        for (int mt = 0; mt < 2; mt++)
            #pragma unroll
            for (int nt = 0; nt < 8; nt++) {
                mma16816(acc[mt][nt], ah[mt], bh[nt]);
                mma16816(acc[mt][nt], ah[mt], bl[nt]);
                mma16816(acc[mt][nt], al[mt], bh[nt]);
            }
    }

    // epilogue: bias + store. c0,c1 -> (row, col..col+1); c2,c3 -> row+8.
    const int gid = lane >> 2, tig = lane & 3;
    #pragma unroll
    for (int mt = 0; mt < 2; mt++) {
        int rlo = row0 + wm * 32 + mt * 16 + gid;
        #pragma unroll
        for (int nt = 0; nt < 8; nt++) {
            int col = wn * 64 + nt * 8 + tig * 2;
            float b0 = __ldg(bias + col);
            float b1 = __ldg(bias + col + 1);
            if (rlo < NN)
                *(float2*)(dst + (size_t)rlo * 128 + col) =
                    make_float2(acc[mt][nt][0] + b0, acc[mt][nt][1] + b1);
            if (rlo + 8 < NN)
                *(float2*)(dst + (size_t)(rlo + 8) * 128 + col) =
                    make_float2(acc[mt][nt][2] + b0, acc[mt][nt][3] + b1);
        }
    }
}

// ---------------- kernel 2: qe = We_h^T q   [N,2,128] ----------------
#define QE_SMEM ((64 * 68 + 64 * 132) * 4)
__global__ void __launch_bounds__(256)
qe_kernel(const float* __restrict__ We)
{
    extern __shared__ float sm[];
    float* As = sm;              // [64 rows][stride 68] (K=64)
    float* Bs = sm + 64 * 68;    // [c=64][stride 132]  Bs[c][j] = We[j*128+h*64+c]

    const int tid = threadIdx.x;
    const int h = blockIdx.y;
    const int row0 = blockIdx.x * 64;

    #pragma unroll
    for (int i = 0; i < 32; i++) {
        int idx = i * 256 + tid;
        int j = idx >> 6, c = idx & 63;
        Bs[c * 132 + j] = We[j * 128 + h * 64 + c];
    }
    #pragma unroll
    for (int i = 0; i < 4; i++) {
        int idx4 = i * 256 + tid;
        int r = idx4 >> 4, c4 = idx4 & 15;
        float4 v = make_float4(0.f, 0.f, 0.f, 0.f);
        if (row0 + r < NN) v = *(const float4*)(g_q + (size_t)(row0 + r) * 128 + h * 64 + c4 * 4);
        *(float4*)(As + r * 68 + c4 * 4) = v;
    }
    __syncthreads();

    const int tx = tid & 15;
    const int ty = tid >> 4;
    const int j0 = tx * 8;
    const int r0 = ty * 4;

    float acc[4][8];
    #pragma unroll
    for (int i = 0; i < 4; i++)
        #pragma unroll
        for (int j = 0; j < 8; j++) acc[i][j] = 0.f;

    #pragma unroll 4
    for (int c = 0; c < 64; c++) {
        float4 b0 = *(const float4*)(Bs + c * 132 + j0);
        float4 b1 = *(const float4*)(Bs + c * 132 + j0 + 4);
        #pragma unroll
        for (int i = 0; i < 4; i++) {
            float a = As[(r0 + i) * 68 + c];
            acc[i][0] += a * b0.x; acc[i][1] += a * b0.y;
            acc[i][2] += a * b0.z; acc[i][3] += a * b0.w;
            acc[i][4] += a * b1.x; acc[i][5] += a * b1.y;
            acc[i][6] += a * b1.z; acc[i][7] += a * b1.w;
        }
    }

    #pragma unroll
    for (int i = 0; i < 4; i++) {
        int r = row0 + r0 + i;
        if (r < NN) {
            float* dstp = g_qe + (size_t)r * 256 + h * 128 + j0;
            *(float4*)(dstp)     = make_float4(acc[i][0], acc[i][1], acc[i][2], acc[i][3]);
            *(float4*)(dstp + 4) = make_float4(acc[i][4], acc[i][5], acc[i][6], acc[i][7]);
        }
    }
}

// ---------------- kernel 3: per-edge time-enc + alpha ----------------
__global__ void __launch_bounds__(256)
edge_kernel(const float* __restrict__ last_update,
            const int* __restrict__ eidx,
            const float* __restrict__ t,
            const float* __restrict__ msg,
            const float* __restrict__ wt,
            const float* __restrict__ bt)
{
    __shared__ float sts[32 * 68];
    __shared__ float swt[64], sbt[64];

    const int tid = threadIdx.x;
    if (tid < 64) { swt[tid] = wt[tid]; sbt[tid] = bt[tid]; }
    __syncthreads();

    const int w = tid >> 5, lane = tid & 31;
    const int g = lane >> 3, l = lane & 7;
    const int le = w * 4 + g;
    const int e = blockIdx.x * 32 + le;

    const int s = eidx[e];
    const int d = eidx[EE + e];
    const float rt = last_update[s] - t[e];

    float tsv[8];
    #pragma unroll
    for (int u = 0; u < 8; u++) {
        int c = l * 8 + u;
        tsv[u] = cos_fast(fmaf(rt, swt[c], sbt[c]));
    }
    *(float4*)(sts + le * 68 + l * 8)     = make_float4(tsv[0], tsv[1], tsv[2], tsv[3]);
    *(float4*)(sts + le * 68 + l * 8 + 4) = make_float4(tsv[4], tsv[5], tsv[6], tsv[7]);
    __syncwarp();

    const float4* q4 = (const float4*)g_q;
    const float4* k4 = (const float4*)g_k;
    const float4* msg4 = (const float4*)msg;
    const float4* qe4 = (const float4*)g_qe;

    size_t qb = (size_t)d * 32, kb = (size_t)s * 32;
    float ph0 = dot4(q4[qb + l], k4[kb + l]) + dot4(q4[qb + l + 8], k4[kb + l + 8]);
    float ph1 = dot4(q4[qb + l + 16], k4[kb + l + 16]) + dot4(q4[qb + l + 24], k4[kb + l + 24]);

    float4 tsA = *(const float4*)(sts + le * 68 + l * 4);
    float4 tsB = *(const float4*)(sts + le * 68 + l * 4 + 32);
    float4 m0 = msg4[(size_t)e * 16 + l];
    float4 m1 = msg4[(size_t)e * 16 + l + 8];
    size_t qeb = (size_t)d * 64;
    ph0 += dot4(qe4[qeb + l], tsA) + dot4(qe4[qeb + l + 8], tsB)
         + dot4(qe4[qeb + l + 16], m0) + dot4(qe4[qeb + l + 24], m1);
    ph1 += dot4(qe4[qeb + 32 + l], tsA) + dot4(qe4[qeb + 32 + l + 8], tsB)
         + dot4(qe4[qeb + 32 + l + 16], m0) + dot4(qe4[qeb + 32 + l + 24], m1);

    #pragma unroll
    for (int o = 4; o; o >>= 1) {
        ph0 += __shfl_xor_sync(0xffffffffu, ph0, o);
        ph1 += __shfl_xor_sync(0xffffffffu, ph1, o);
    }
    if (l == 0)
        *(float2*)(g_alpha + (size_t)e * 2) = make_float2(ph0 * 0.125f, ph1 * 0.125f);
}

// ---------------- kernel 4: segment max ----------------
__global__ void amax_kernel(const int* __restrict__ eidx) {
    int i = blockIdx.x * blockDim.x + threadIdx.x;
    if (i >= EE * 2) return;
    int e = i >> 1;
    int h = i & 1;
    int d = eidx[EE + e];
    atomicMaxF(&g_amax[d * 2 + h], g_alpha[i]);
}

// ---------------- kernel 5: exp + segment sum ----------------
__global__ void ex_kernel(const int* __restrict__ eidx) {
    int i = blockIdx.x * blockDim.x + threadIdx.x;
    if (i >= EE * 2) return;
    int e = i >> 1;
    int h = i & 1;
    int d = eidx[EE + e];
    float ex = expf(g_alpha[i] - g_amax[d * 2 + h]);
    g_ex[i] = ex;
    atomicAdd(&g_denom[d * 2 + h], ex);
}

// ---------------- kernel 6: scatter attn*v -> out, attn*edge_attr -> accA ----------------
// time encoding recomputed in-kernel (saves 308MB of DRAM vs storing it)
__global__ void __launch_bounds__(256)
agg_kernel(const int* __restrict__ eidx, const float* __restrict__ msg,
           const float* __restrict__ last_update, const float* __restrict__ t,
           const float* __restrict__ wt, const float* __restrict__ bt,
           float* __restrict__ out)
{
    __shared__ float swt[64], sbt[64];
    const int tid = threadIdx.x;
    if (tid < 64) { swt[tid] = wt[tid]; sbt[tid] = bt[tid]; }
    __syncthreads();

    const int w = tid >> 5, lane = tid & 31;
    const int g = lane >> 3, l = lane & 7;
    const int e = blockIdx.x * 32 + w * 4 + g;

    const int s = eidx[e];
    const int d = eidx[EE + e];
    float2 exv = *(const float2*)(g_ex + (size_t)e * 2);
    float2 dn = *(const float2*)(g_denom + (size_t)d * 2);
    float a0 = exv.x / (dn.x + 1e-16f);
    float a1 = exv.y / (dn.y + 1e-16f);

    const float4* v4 = (const float4*)g_v;
    size_t vb = (size_t)s * 32;
    float* ob = out + (size_t)d * 128;
    {
        float4 va = v4[vb + l], vbc = v4[vb + l + 8];
        float4 vc = v4[vb + l + 16], vd = v4[vb + l + 24];
        red4(ob + l * 4,        make_float4(a0 * va.x, a0 * va.y, a0 * va.z, a0 * va.w));
        red4(ob + (l + 8) * 4,  make_float4(a0 * vbc.x, a0 * vbc.y, a0 * vbc.z, a0 * vbc.w));
        red4(ob + (l + 16) * 4, make_float4(a1 * vc.x, a1 * vc.y, a1 * vc.z, a1 * vc.w));
        red4(ob + (l + 24) * 4, make_float4(a1 * vd.x, a1 * vd.y, a1 * vd.z, a1 * vd.w));
    }

    // recompute time encoding channels 4l..4l+3 and 32+4l..32+4l+3
    const float rt = last_update[s] - t[e];
    float4 tsA, tsB;
    {
        int cA = l * 4, cB = 32 + l * 4;
        tsA.x = cos_fast(fmaf(rt, swt[cA + 0], sbt[cA + 0]));
        tsA.y = cos_fast(fmaf(rt, swt[cA + 1], sbt[cA + 1]));
        tsA.z = cos_fast(fmaf(rt, swt[cA + 2], sbt[cA + 2]));
        tsA.w = cos_fast(fmaf(rt, swt[cA + 3], sbt[cA + 3]));
        tsB.x = cos_fast(fmaf(rt, swt[cB + 0], sbt[cB + 0]));
        tsB.y = cos_fast(fmaf(rt, swt[cB + 1], sbt[cB + 1]));
        tsB.z = cos_fast(fmaf(rt, swt[cB + 2], sbt[cB + 2]));
        tsB.w = cos_fast(fmaf(rt, swt[cB + 3], sbt[cB + 3]));
    }

    const float4* msg4 = (const float4*)msg;
    float4 m0 = msg4[(size_t)e * 16 + l];
    float4 m1 = msg4[(size_t)e * 16 + l + 8];
    float* A = g_accA + (size_t)d * 256;
    red4(A + l * 4,              make_float4(a0 * tsA.x, a0 * tsA.y, a0 * tsA.z, a0 * tsA.w));
    red4(A + (l + 8) * 4,        make_float4(a0 * tsB.x, a0 * tsB.y, a0 * tsB.z, a0 * tsB.w));
    red4(A + (l + 16) * 4,       make_float4(a0 * m0.x, a0 * m0.y, a0 * m0.z, a0 * m0.w));
    red4(A + (l + 24) * 4,       make_float4(a0 * m1.x, a0 * m1.y, a0 * m1.z, a0 * m1.w));
    red4(A + 128 + l * 4,        make_float4(a1 * tsA.x, a1 * tsA.y, a1 * tsA.z, a1 * tsA.w));
    red4(A + 128 + (l + 8) * 4,  make_float4(a1 * tsB.x, a1 * tsB.y, a1 * tsB.z, a1 * tsB.w));
    red4(A + 128 + (l + 16) * 4, make_float4(a1 * m0.x, a1 * m0.y, a1 * m0.z, a1 * m0.w));
    red4(A + 128 + (l + 24) * 4, make_float4(a1 * m1.x, a1 * m1.y, a1 * m1.z, a1 * m1.w));
}

// ---------------- kernel 7: epilogue  out += accA_h @ We_h ----------------
#define EPI_SMEM ((64 * 132 + 128 * 68) * 4)
__global__ void __launch_bounds__(256)
epi_kernel(const float* __restrict__ We, float* __restrict__ out)
{
    extern __shared__ float sm[];
    float* As = sm;               // [64 rows][stride 132] K=128
    float* Bs = sm + 64 * 132;    // [d=128][stride 68] c=0..63

    const int tid = threadIdx.x;
    const int h = blockIdx.y;
    const int row0 = blockIdx.x * 64;

    #pragma unroll
    for (int i = 0; i < 32; i++) {
        int idx = i * 256 + tid;
        int dd = idx >> 6, c = idx & 63;
        Bs[dd * 68 + c] = We[dd * 128 + h * 64 + c];
    }
    #pragma unroll
    for (int i = 0; i < 8; i++) {
        int idx4 = i * 256 + tid;
        int r = idx4 >> 5, k4 = idx4 & 31;
        float4 v = make_float4(0.f, 0.f, 0.f, 0.f);
        if (row0 + r < NN) v = *(const float4*)(g_accA + (size_t)(row0 + r) * 256 + h * 128 + k4 * 4);
        *(float4*)(As + r * 132 + k4 * 4) = v;
    }
    __syncthreads();

    const int tx = tid & 15;
    const int ty = tid >> 4;
    const int c0 = tx * 4;
    const int r0 = ty * 4;

    float acc[4][4];
    #pragma unroll
    for (int i = 0; i < 4; i++)
        #pragma unroll
        for (int j = 0; j < 4; j++) acc[i][j] = 0.f;

    #pragma unroll 4
    for (int k = 0; k < 128; k++) {
        float4 b = *(const float4*)(Bs + k * 68 + c0);
        #pragma unroll
        for (int i = 0; i < 4; i++) {
            float a = As[(r0 + i) * 132 + k];
            acc[i][0] += a * b.x; acc[i][1] += a * b.y;
            acc[i][2] += a * b.z; acc[i][3] += a * b.w;
        }
    }

    #pragma unroll
    for (int i = 0; i < 4; i++) {
        int r = row0 + r0 + i;
        if (r < NN) {
            float* p = out + (size_t)r * 128 + h * 64 + c0;
            float4 cur = *(float4*)p;
            cur.x += acc[i][0]; cur.y += acc[i][1];
            cur.z += acc[i][2]; cur.w += acc[i][3];
            *(float4*)p = cur;
        }
    }
}

// ---------------- launch ----------------
extern "C" void kernel_launch(void* const* d_in, const int* in_sizes, int n_in,
                              void* d_out, int out_size) {
    const float* x    = (const float*)d_in[0];
    const float* lu   = (const float*)d_in[1];
    const int*   eidx = (const int*)d_in[2];
    const float* t    = (const float*)d_in[3];
    const float* msg  = (const float*)d_in[4];
    const float* wt   = (const float*)d_in[5];
    const float* bt   = (const float*)d_in[6];
    const float* Wq   = (const float*)d_in[7];
    const float* bq   = (const float*)d_in[8];
    const float* Wk   = (const float*)d_in[9];
    const float* bk   = (const float*)d_in[10];
    const float* Wv   = (const float*)d_in[11];
    const float* bv   = (const float*)d_in[12];
    const float* We   = (const float*)d_in[13];
    const float* Wsk  = (const float*)d_in[14];
    const float* bsk  = (const float*)d_in[15];
    float* out = (float*)d_out;

    cudaFuncSetAttribute(node_mma_kernel, cudaFuncAttributeMaxDynamicSharedMemorySize, NODE_SMEM);
    cudaFuncSetAttribute(qe_kernel,       cudaFuncAttributeMaxDynamicSharedMemorySize, QE_SMEM);
    cudaFuncSetAttribute(epi_kernel,      cudaFuncAttributeMaxDynamicSharedMemorySize, EPI_SMEM);

    init_kernel<<<(NN * 64 + 255) / 256, 256>>>();
    node_mma_kernel<<<dim3((NN + 127) / 128, 4), 256, NODE_SMEM>>>(
        x, Wq, bq, Wk, bk, Wv, bv, Wsk, bsk, out);
    qe_kernel<<<dim3((NN + 63) / 64, 2), 256, QE_SMEM>>>(We);
    edge_kernel<<<EE / 32, 256>>>(lu, eidx, t, msg, wt, bt);
    amax_kernel<<<(EE * 2 + 255) / 256, 256>>>(eidx);
    ex_kernel<<<(EE * 2 + 255) / 256, 256>>>(eidx);
    agg_kernel<<<EE / 32, 256>>>(eidx, msg, lu, t, wt, bt, out);
    epi_kernel<<<dim3((NN + 63) / 64, 2), 256, EPI_SMEM>>>(We, out);
}

// round 10
// speedup vs baseline: 1.0266x; 1.0266x over previous
#include <cuda_runtime.h>
#include <math_constants.h>

#define NN 100000
#define EE 600000

// ---------------- scratch ----------------
__device__ float g_q[NN * 128];
__device__ float g_k[NN * 128];
__device__ float g_v[NN * 128];
__device__ float g_qe[(size_t)NN * 256];    // per-node, per-head We^T q
__device__ float g_accA[(size_t)NN * 256];  // attn-weighted edge_attr sums
__device__ float g_alpha[EE * 2];
__device__ int   g_cnt[NN];
__device__ int   g_off[NN + 1];
__device__ int   g_cur[NN];
__device__ int   g_eord[EE];

__device__ __forceinline__ float dot4(float4 a, float4 b) {
    return a.x * b.x + a.y * b.y + a.z * b.z + a.w * b.w;
}

// accurate cos: manual 2pi range reduction + MUFU
__device__ __forceinline__ float cos_fast(float x) {
    float kq = rintf(x * 0.15915494309189535f);
    float r = fmaf(kq, -6.28318548202514648f, x);
    r = fmaf(kq, 1.74845553e-07f, r);
    return __cosf(r);
}

// ---------------- kernel 0: zero hist counters ----------------
__global__ void zero_cnt_kernel() {
    int i = blockIdx.x * blockDim.x + threadIdx.x;
    if (i < NN) g_cnt[i] = 0;
}

// ---------------- kernel 1: node projections (q,k,v,skip) — FFMA ----------------
#define NODE_SMEM ((16384 + 64 * 132) * 4)
__global__ void node_gemm_kernel(const float* __restrict__ x,
                                 const float* __restrict__ Wq, const float* __restrict__ bq,
                                 const float* __restrict__ Wk, const float* __restrict__ bk,
                                 const float* __restrict__ Wv, const float* __restrict__ bv,
                                 const float* __restrict__ Wsk, const float* __restrict__ bsk,
                                 float* __restrict__ out_skip)
{
    extern __shared__ float sm[];
    float* Ws = sm;             // 128*128
    float* xs = sm + 16384;     // 64 rows * stride 132

    const int tid = threadIdx.x;
    const float* W; const float* bias; float* dst;
    switch (blockIdx.y) {
        case 0:  W = Wq;  bias = bq;  dst = g_q;      break;
        case 1:  W = Wk;  bias = bk;  dst = g_k;      break;
        case 2:  W = Wv;  bias = bv;  dst = g_v;      break;
        default: W = Wsk; bias = bsk; dst = out_skip; break;
    }

    {
        const float4* W4 = (const float4*)W;
        float4* Ws4 = (float4*)Ws;
        #pragma unroll
        for (int i = 0; i < 16; i++) Ws4[i * 256 + tid] = W4[i * 256 + tid];
    }
    const int row0 = blockIdx.x * 64;
    {
        #pragma unroll
        for (int i = 0; i < 8; i++) {
            int idx = i * 256 + tid;
            int r = idx >> 5;
            int c4 = idx & 31;
            float4 v = make_float4(0.f, 0.f, 0.f, 0.f);
            if (row0 + r < NN) v = ((const float4*)x)[(row0 + r) * 32 + c4];
            *(float4*)(xs + r * 132 + c4 * 4) = v;
        }
    }
    __syncthreads();

    const int tx = tid & 15;
    const int ty = tid >> 4;
    const int c0 = tx * 8;
    const int r0 = ty * 4;

    float acc[4][8];
    #pragma unroll
    for (int i = 0; i < 4; i++)
        #pragma unroll
        for (int j = 0; j < 8; j++) acc[i][j] = 0.f;

    #pragma unroll 4
    for (int k = 0; k < 128; k++) {
        float4 b0 = *(const float4*)(Ws + k * 128 + c0);
        float4 b1 = *(const float4*)(Ws + k * 128 + c0 + 4);
        #pragma unroll
        for (int i = 0; i < 4; i++) {
            float a = xs[(r0 + i) * 132 + k];
            acc[i][0] += a * b0.x; acc[i][1] += a * b0.y;
            acc[i][2] += a * b0.z; acc[i][3] += a * b0.w;
            acc[i][4] += a * b1.x; acc[i][5] += a * b1.y;
            acc[i][6] += a * b1.z; acc[i][7] += a * b1.w;
        }
    }

    float bb[8];
    #pragma unroll
    for (int j = 0; j < 8; j++) bb[j] = __ldg(bias + c0 + j);

    #pragma unroll
    for (int i = 0; i < 4; i++) {
        int r = row0 + r0 + i;
        if (r < NN) {
            float4 o0 = make_float4(acc[i][0] + bb[0], acc[i][1] + bb[1],
                                    acc[i][2] + bb[2], acc[i][3] + bb[3]);
            float4 o1 = make_float4(acc[i][4] + bb[4], acc[i][5] + bb[5],
                                    acc[i][6] + bb[6], acc[i][7] + bb[7]);
            *(float4*)(dst + r * 128 + c0)     = o0;
            *(float4*)(dst + r * 128 + c0 + 4) = o1;
        }
    }
}

// ---------------- kernel 2: qe = We_h^T q   [N,2,128] ----------------
#define QE_SMEM ((64 * 68 + 64 * 132) * 4)
__global__ void __launch_bounds__(256)
qe_kernel(const float* __restrict__ We)
{
    extern __shared__ float sm[];
    float* As = sm;              // [64 rows][stride 68] (K=64)
    float* Bs = sm + 64 * 68;    // [c=64][stride 132]

    const int tid = threadIdx.x;
    const int h = blockIdx.y;
    const int row0 = blockIdx.x * 64;

    #pragma unroll
    for (int i = 0; i < 32; i++) {
        int idx = i * 256 + tid;
        int j = idx >> 6, c = idx & 63;
        Bs[c * 132 + j] = We[j * 128 + h * 64 + c];
    }
    #pragma unroll
    for (int i = 0; i < 4; i++) {
        int idx4 = i * 256 + tid;
        int r = idx4 >> 4, c4 = idx4 & 15;
        float4 v = make_float4(0.f, 0.f, 0.f, 0.f);
        if (row0 + r < NN) v = *(const float4*)(g_q + (size_t)(row0 + r) * 128 + h * 64 + c4 * 4);
        *(float4*)(As + r * 68 + c4 * 4) = v;
    }
    __syncthreads();

    const int tx = tid & 15;
    const int ty = tid >> 4;
    const int j0 = tx * 8;
    const int r0 = ty * 4;

    float acc[4][8];
    #pragma unroll
    for (int i = 0; i < 4; i++)
        #pragma unroll
        for (int j = 0; j < 8; j++) acc[i][j] = 0.f;

    #pragma unroll 4
    for (int c = 0; c < 64; c++) {
        float4 b0 = *(const float4*)(Bs + c * 132 + j0);
        float4 b1 = *(const float4*)(Bs + c * 132 + j0 + 4);
        #pragma unroll
        for (int i = 0; i < 4; i++) {
            float a = As[(r0 + i) * 68 + c];
            acc[i][0] += a * b0.x; acc[i][1] += a * b0.y;
            acc[i][2] += a * b0.z; acc[i][3] += a * b0.w;
            acc[i][4] += a * b1.x; acc[i][5] += a * b1.y;
            acc[i][6] += a * b1.z; acc[i][7] += a * b1.w;
        }
    }

    #pragma unroll
    for (int i = 0; i < 4; i++) {
        int r = row0 + r0 + i;
        if (r < NN) {
            float* dstp = g_qe + (size_t)r * 256 + h * 128 + j0;
            *(float4*)(dstp)     = make_float4(acc[i][0], acc[i][1], acc[i][2], acc[i][3]);
            *(float4*)(dstp + 4) = make_float4(acc[i][4], acc[i][5], acc[i][6], acc[i][7]);
        }
    }
}

// ---------------- kernel 3: per-edge time-enc + alpha (+ dst histogram) ----------------
__global__ void __launch_bounds__(256)
edge_kernel(const float* __restrict__ last_update,
            const int* __restrict__ eidx,
            const float* __restrict__ t,
            const float* __restrict__ msg,
            const float* __restrict__ wt,
            const float* __restrict__ bt)
{
    __shared__ float sts[32 * 68];
    __shared__ float swt[64], sbt[64];

    const int tid = threadIdx.x;
    if (tid < 64) { swt[tid] = wt[tid]; sbt[tid] = bt[tid]; }
    __syncthreads();

    const int w = tid >> 5, lane = tid & 31;
    const int g = lane >> 3, l = lane & 7;
    const int le = w * 4 + g;
    const int e = blockIdx.x * 32 + le;

    const int s = eidx[e];
    const int d = eidx[EE + e];
    const float rt = last_update[s] - t[e];

    if (l == 0) atomicAdd(&g_cnt[d], 1);   // histogram for counting sort

    float tsv[8];
    #pragma unroll
    for (int u = 0; u < 8; u++) {
        int c = l * 8 + u;
        tsv[u] = cos_fast(fmaf(rt, swt[c], sbt[c]));
    }
    *(float4*)(sts + le * 68 + l * 8)     = make_float4(tsv[0], tsv[1], tsv[2], tsv[3]);
    *(float4*)(sts + le * 68 + l * 8 + 4) = make_float4(tsv[4], tsv[5], tsv[6], tsv[7]);
    __syncwarp();

    const float4* q4 = (const float4*)g_q;
    const float4* k4 = (const float4*)g_k;
    const float4* msg4 = (const float4*)msg;
    const float4* qe4 = (const float4*)g_qe;

    size_t qb = (size_t)d * 32, kb = (size_t)s * 32;
    float ph0 = dot4(q4[qb + l], k4[kb + l]) + dot4(q4[qb + l + 8], k4[kb + l + 8]);
    float ph1 = dot4(q4[qb + l + 16], k4[kb + l + 16]) + dot4(q4[qb + l + 24], k4[kb + l + 24]);

    float4 tsA = *(const float4*)(sts + le * 68 + l * 4);
    float4 tsB = *(const float4*)(sts + le * 68 + l * 4 + 32);
    float4 m0 = msg4[(size_t)e * 16 + l];
    float4 m1 = msg4[(size_t)e * 16 + l + 8];
    size_t qeb = (size_t)d * 64;
    ph0 += dot4(qe4[qeb + l], tsA) + dot4(qe4[qeb + l + 8], tsB)
         + dot4(qe4[qeb + l + 16], m0) + dot4(qe4[qeb + l + 24], m1);
    ph1 += dot4(qe4[qeb + 32 + l], tsA) + dot4(qe4[qeb + 32 + l + 8], tsB)
         + dot4(qe4[qeb + 32 + l + 16], m0) + dot4(qe4[qeb + 32 + l + 24], m1);

    #pragma unroll
    for (int o = 4; o; o >>= 1) {
        ph0 += __shfl_xor_sync(0xffffffffu, ph0, o);
        ph1 += __shfl_xor_sync(0xffffffffu, ph1, o);
    }
    if (l == 0)
        *(float2*)(g_alpha + (size_t)e * 2) = make_float2(ph0 * 0.125f, ph1 * 0.125f);
}

// ---------------- kernel 4: exclusive prefix scan of g_cnt (single block) ----------------
__global__ void __launch_bounds__(1024)
scan_kernel()
{
    __shared__ int warpsum[32];
    __shared__ int carry;
    const int tid = threadIdx.x;
    const int wid = tid >> 5, lane = tid & 31;
    if (tid == 0) carry = 0;
    __syncthreads();

    for (int base = 0; base < NN; base += 1024) {
        int i = base + tid;
        int v = (i < NN) ? g_cnt[i] : 0;
        int x = v;
        #pragma unroll
        for (int o = 1; o < 32; o <<= 1) {
            int y = __shfl_up_sync(0xffffffffu, x, o);
            if (lane >= o) x += y;
        }
        if (lane == 31) warpsum[wid] = x;
        __syncthreads();
        if (tid < 32) {
            int s_ = warpsum[tid];
            #pragma unroll
            for (int o = 1; o < 32; o <<= 1) {
                int y = __shfl_up_sync(0xffffffffu, s_, o);
                if (tid >= o) s_ += y;
            }
            warpsum[tid] = s_;
        }
        __syncthreads();
        int incl = x + (wid > 0 ? warpsum[wid - 1] : 0) + carry;
        if (i < NN) {
            g_off[i] = incl - v;
            g_cur[i] = incl - v;
        }
        __syncthreads();
        if (tid == 0) carry += warpsum[31];
        __syncthreads();
    }
    if (threadIdx.x == 0) g_off[NN] = carry;
}

// ---------------- kernel 5: scatter edges into dst-sorted order ----------------
__global__ void scatter_kernel(const int* __restrict__ eidx) {
    int e = blockIdx.x * blockDim.x + threadIdx.x;
    if (e >= EE) return;
    int d = eidx[EE + e];
    int pos = atomicAdd(&g_cur[d], 1);
    g_eord[pos] = e;
}

// ---------------- kernel 6: per-dst softmax + aggregation (no atomics) ----------------
// one warp per dst node. lane covers 4 channels (c = lane*4).
__global__ void __launch_bounds__(256)
agg_kernel(const int* __restrict__ eidx, const float* __restrict__ msg,
           const float* __restrict__ last_update, const float* __restrict__ t,
           const float* __restrict__ wt, const float* __restrict__ bt,
           float* __restrict__ out)
{
    __shared__ float swt[64], sbt[64];
    const int tid = threadIdx.x;
    if (tid < 64) { swt[tid] = wt[tid]; sbt[tid] = bt[tid]; }
    __syncthreads();

    const int d = blockIdx.x * 8 + (tid >> 5);
    const int lane = tid & 31;

    const int beg = g_off[d];
    const int n = g_off[d + 1] - beg;

    float aO[4]  = {0.f, 0.f, 0.f, 0.f};
    float aA0[4] = {0.f, 0.f, 0.f, 0.f};
    float aA1[4] = {0.f, 0.f, 0.f, 0.f};

    if (n > 0) {
        // pass 1: per-head max
        float m0 = -CUDART_INF_F, m1 = -CUDART_INF_F;
        for (int j = lane; j < n; j += 32) {
            int e = g_eord[beg + j];
            float2 al = *(const float2*)(g_alpha + (size_t)e * 2);
            m0 = fmaxf(m0, al.x);
            m1 = fmaxf(m1, al.y);
        }
        #pragma unroll
        for (int o = 16; o; o >>= 1) {
            m0 = fmaxf(m0, __shfl_xor_sync(0xffffffffu, m0, o));
            m1 = fmaxf(m1, __shfl_xor_sync(0xffffffffu, m1, o));
        }
        // pass 2: denom
        float s0 = 0.f, s1 = 0.f;
        for (int j = lane; j < n; j += 32) {
            int e = g_eord[beg + j];
            float2 al = *(const float2*)(g_alpha + (size_t)e * 2);
            s0 += expf(al.x - m0);
            s1 += expf(al.y - m1);
        }
        #pragma unroll
        for (int o = 16; o; o >>= 1) {
            s0 += __shfl_xor_sync(0xffffffffu, s0, o);
            s1 += __shfl_xor_sync(0xffffffffu, s1, o);
        }
        const float inv0 = 1.f / (s0 + 1e-16f);
        const float inv1 = 1.f / (s1 + 1e-16f);

        // pass 3: aggregate
        for (int j = 0; j < n; j++) {
            int e = g_eord[beg + j];
            int s = eidx[e];
            float2 al = *(const float2*)(g_alpha + (size_t)e * 2);
            float a0 = expf(al.x - m0) * inv0;
            float a1 = expf(al.y - m1) * inv1;

            float4 v4 = ((const float4*)g_v)[(size_t)s * 32 + lane];
            float ah = (lane < 16) ? a0 : a1;
            aO[0] += ah * v4.x; aO[1] += ah * v4.y;
            aO[2] += ah * v4.z; aO[3] += ah * v4.w;

            float4 ea;
            if (lane < 16) {
                float rt = last_update[s] - t[e];
                int c = lane * 4;
                ea.x = cos_fast(fmaf(rt, swt[c + 0], sbt[c + 0]));
                ea.y = cos_fast(fmaf(rt, swt[c + 1], sbt[c + 1]));
                ea.z = cos_fast(fmaf(rt, swt[c + 2], sbt[c + 2]));
                ea.w = cos_fast(fmaf(rt, swt[c + 3], sbt[c + 3]));
            } else {
                ea = ((const float4*)msg)[(size_t)e * 16 + (lane - 16)];
            }
            aA0[0] += a0 * ea.x; aA0[1] += a0 * ea.y;
            aA0[2] += a0 * ea.z; aA0[3] += a0 * ea.w;
            aA1[0] += a1 * ea.x; aA1[1] += a1 * ea.y;
            aA1[2] += a1 * ea.z; aA1[3] += a1 * ea.w;
        }

        // accumulate onto skip value already in out
        float4* op = (float4*)out + (size_t)d * 32 + lane;
        float4 cur = *op;
        cur.x += aO[0]; cur.y += aO[1]; cur.z += aO[2]; cur.w += aO[3];
        *op = cur;
    }

    ((float4*)g_accA)[(size_t)d * 64 + lane]      = make_float4(aA0[0], aA0[1], aA0[2], aA0[3]);
    ((float4*)g_accA)[(size_t)d * 64 + 32 + lane] = make_float4(aA1[0], aA1[1], aA1[2], aA1[3]);
}

// ---------------- kernel 7: epilogue  out += accA_h @ We_h ----------------
#define EPI_SMEM ((64 * 132 + 128 * 68) * 4)
__global__ void __launch_bounds__(256)
epi_kernel(const float* __restrict__ We, float* __restrict__ out)
{
    extern __shared__ float sm[];
    float* As = sm;               // [64 rows][stride 132] K=128
    float* Bs = sm + 64 * 132;    // [d=128][stride 68] c=0..63

    const int tid = threadIdx.x;
    const int h = blockIdx.y;
    const int row0 = blockIdx.x * 64;

    #pragma unroll
    for (int i = 0; i < 32; i++) {
        int idx = i * 256 + tid;
        int dd = idx >> 6, c = idx & 63;
        Bs[dd * 68 + c] = We[dd * 128 + h * 64 + c];
    }
    #pragma unroll
    for (int i = 0; i < 8; i++) {
        int idx4 = i * 256 + tid;
        int r = idx4 >> 5, k4 = idx4 & 31;
        float4 v = make_float4(0.f, 0.f, 0.f, 0.f);
        if (row0 + r < NN) v = *(const float4*)(g_accA + (size_t)(row0 + r) * 256 + h * 128 + k4 * 4);
        *(float4*)(As + r * 132 + k4 * 4) = v;
    }
    __syncthreads();

    const int tx = tid & 15;
    const int ty = tid >> 4;
    const int c0 = tx * 4;
    const int r0 = ty * 4;

    float acc[4][4];
    #pragma unroll
    for (int i = 0; i < 4; i++)
        #pragma unroll
        for (int j = 0; j < 4; j++) acc[i][j] = 0.f;

    #pragma unroll 4
    for (int k = 0; k < 128; k++) {
        float4 b = *(const float4*)(Bs + k * 68 + c0);
        #pragma unroll
        for (int i = 0; i < 4; i++) {
            float a = As[(r0 + i) * 132 + k];
            acc[i][0] += a * b.x; acc[i][1] += a * b.y;
            acc[i][2] += a * b.z; acc[i][3] += a * b.w;
        }
    }

    #pragma unroll
    for (int i = 0; i < 4; i++) {
        int r = row0 + r0 + i;
        if (r < NN) {
            float* p = out + (size_t)r * 128 + h * 64 + c0;
            float4 cur = *(float4*)p;
            cur.x += acc[i][0]; cur.y += acc[i][1];
            cur.z += acc[i][2]; cur.w += acc[i][3];
            *(float4*)p = cur;
        }
    }
}

// ---------------- launch ----------------
extern "C" void kernel_launch(void* const* d_in, const int* in_sizes, int n_in,
                              void* d_out, int out_size) {
    const float* x    = (const float*)d_in[0];
    const float* lu   = (const float*)d_in[1];
    const int*   eidx = (const int*)d_in[2];
    const float* t    = (const float*)d_in[3];
    const float* msg  = (const float*)d_in[4];
    const float* wt   = (const float*)d_in[5];
    const float* bt   = (const float*)d_in[6];
    const float* Wq   = (const float*)d_in[7];
    const float* bq   = (const float*)d_in[8];
    const float* Wk   = (const float*)d_in[9];
    const float* bk   = (const float*)d_in[10];
    const float* Wv   = (const float*)d_in[11];
    const float* bv   = (const float*)d_in[12];
    const float* We   = (const float*)d_in[13];
    const float* Wsk  = (const float*)d_in[14];
    const float* bsk  = (const float*)d_in[15];
    float* out = (float*)d_out;

    cudaFuncSetAttribute(node_gemm_kernel, cudaFuncAttributeMaxDynamicSharedMemorySize, NODE_SMEM);
    cudaFuncSetAttribute(qe_kernel,        cudaFuncAttributeMaxDynamicSharedMemorySize, QE_SMEM);
    cudaFuncSetAttribute(epi_kernel,       cudaFuncAttributeMaxDynamicSharedMemorySize, EPI_SMEM);

    zero_cnt_kernel<<<(NN + 255) / 256, 256>>>();
    node_gemm_kernel<<<dim3((NN + 63) / 64, 4), 256, NODE_SMEM>>>(
        x, Wq, bq, Wk, bk, Wv, bv, Wsk, bsk, out);
    qe_kernel<<<dim3((NN + 63) / 64, 2), 256, QE_SMEM>>>(We);
    edge_kernel<<<EE / 32, 256>>>(lu, eidx, t, msg, wt, bt);
    scan_kernel<<<1, 1024>>>();
    scatter_kernel<<<(EE + 255) / 256, 256>>>(eidx);
    agg_kernel<<<(NN + 7) / 8, 256>>>(eidx, msg, lu, t, wt, bt, out);
    epi_kernel<<<dim3((NN + 63) / 64, 2), 256, EPI_SMEM>>>(We, out);
}

// round 11
// speedup vs baseline: 1.3963x; 1.3601x over previous
#include <cuda_runtime.h>
#include <cuda_bf16.h>
#include <math_constants.h>

#define NN 100000
#define EE 600000
#define NM16 6250          // NN/16 exactly
#define NM16_PAD 6256      // padded to CTA (128-row = 8 m16) granularity

// ---------------- scratch ----------------
__device__ float g_q[NN * 128];
__device__ float g_k[NN * 128];
__device__ float g_v[NN * 128];
__device__ float g_qe[(size_t)NN * 256];
__device__ float g_accA[(size_t)NN * 256];
__device__ float g_alpha[EE * 2];
__device__ int   g_cnt[NN];
__device__ int   g_off[NN + 1];
__device__ int   g_cur[NN];
__device__ int   g_eord[EE];
// bf16 hi/lo planes, MMA-fragment-ordered
__device__ unsigned g_xA[(size_t)NM16_PAD * 8 * 128];  // hi
__device__ unsigned g_xB[(size_t)NM16_PAD * 8 * 128];  // lo
__device__ unsigned g_wA[4][8192];                     // hi (Wq,Wk,Wv,Wskip)
__device__ unsigned g_wB[4][8192];                     // lo

__device__ __forceinline__ float dot4(float4 a, float4 b) {
    return a.x * b.x + a.y * b.y + a.z * b.z + a.w * b.w;
}

__device__ __forceinline__ float cos_fast(float x) {
    float kq = rintf(x * 0.15915494309189535f);
    float r = fmaf(kq, -6.28318548202514648f, x);
    r = fmaf(kq, 1.74845553e-07f, r);
    return __cosf(r);
}

__device__ __forceinline__ void mma16816(float* c, const unsigned* a, const unsigned* b) {
    asm volatile("mma.sync.aligned.m16n8k16.row.col.f32.bf16.bf16.f32 "
        "{%0,%1,%2,%3},{%4,%5,%6,%7},{%8,%9},{%0,%1,%2,%3};"
        : "+f"(c[0]), "+f"(c[1]), "+f"(c[2]), "+f"(c[3])
        : "r"(a[0]), "r"(a[1]), "r"(a[2]), "r"(a[3]), "r"(b[0]), "r"(b[1]));
}

__device__ __forceinline__ void split2(float vx, float vy, unsigned& hi, unsigned& lo) {
    __nv_bfloat16 hx = __float2bfloat16(vx);
    __nv_bfloat16 hy = __float2bfloat16(vy);
    __nv_bfloat16 lx = __float2bfloat16(vx - __bfloat162float(hx));
    __nv_bfloat16 ly = __float2bfloat16(vy - __bfloat162float(hy));
    hi = (unsigned)__bfloat16_as_ushort(hx) | ((unsigned)__bfloat16_as_ushort(hy) << 16);
    lo = (unsigned)__bfloat16_as_ushort(lx) | ((unsigned)__bfloat16_as_ushort(ly) << 16);
}

// ---------------- kernel A1: convert x -> fragment-ordered bf16 planes ----------------
// block = one m16 row-block (16 rows); warp kk handles k16-block kk.
__global__ void __launch_bounds__(256)
convx_kernel(const float* __restrict__ x)
{
    const int m16 = blockIdx.x;
    const int kk = threadIdx.x >> 5;
    const int lane = threadIdx.x & 31;
    const size_t base = ((size_t)m16 * 8 + kk) * 128 + lane * 4;

    if (m16 >= NM16) {   // pad blocks: zero
        *(uint4*)&g_xA[base] = make_uint4(0, 0, 0, 0);
        *(uint4*)&g_xB[base] = make_uint4(0, 0, 0, 0);
        return;
    }
    const int r0 = m16 * 16 + (lane >> 2);
    const int r1 = r0 + 8;
    const int k0 = kk * 16 + (lane & 3) * 2;

    float2 xa = *(const float2*)(x + (size_t)r0 * 128 + k0);
    float2 xb = *(const float2*)(x + (size_t)r1 * 128 + k0);
    float2 xc = *(const float2*)(x + (size_t)r0 * 128 + k0 + 8);
    float2 xd = *(const float2*)(x + (size_t)r1 * 128 + k0 + 8);

    uint4 hi, lo;
    split2(xa.x, xa.y, hi.x, lo.x);   // reg0: rows 0-7,  k 0-7
    split2(xb.x, xb.y, hi.y, lo.y);   // reg1: rows 8-15, k 0-7
    split2(xc.x, xc.y, hi.z, lo.z);   // reg2: rows 0-7,  k 8-15
    split2(xd.x, xd.y, hi.w, lo.w);   // reg3: rows 8-15, k 8-15
    *(uint4*)&g_xA[base] = hi;
    *(uint4*)&g_xB[base] = lo;
}

// ---------------- kernel A2: convert 4 weight matrices -> fragment-ordered planes ----------------
__global__ void __launch_bounds__(256)
convw_kernel(const float* __restrict__ Wq, const float* __restrict__ Wk,
             const float* __restrict__ Wv, const float* __restrict__ Wsk)
{
    int i = blockIdx.x * blockDim.x + threadIdx.x;   // 0..32767
    if (i >= 4 * 8192) return;
    int wi = i >> 13;
    int u = i & 8191;
    const float* W = (wi == 0) ? Wq : (wi == 1) ? Wk : (wi == 2) ? Wv : Wsk;

    int blk = u >> 6;          // (kk*16 + n8)
    int lane = (u >> 1) & 31;
    int reg = u & 1;
    int kk = blk >> 4, n8 = blk & 15;
    int k = kk * 16 + reg * 8 + (lane & 3) * 2;
    int n = n8 * 8 + (lane >> 2);
    float v0 = W[k * 128 + n];
    float v1 = W[(k + 1) * 128 + n];
    unsigned hi, lo;
    split2(v0, v1, hi, lo);
    g_wA[wi][u] = hi;
    g_wB[wi][u] = lo;
}

// ---------------- kernel 0: zero hist counters ----------------
__global__ void zero_cnt_kernel() {
    int i = blockIdx.x * blockDim.x + threadIdx.x;
    if (i < NN) g_cnt[i] = 0;
}

// ---------------- kernel 1: node projections via preconverted bf16 MMA ----------------
// grid (782, 4). 8 warps: wm 0..3 (32-row), wn 0..1 (64-col). No smem.
__global__ void __launch_bounds__(256, 1)
node_mma_kernel(const float* __restrict__ bq, const float* __restrict__ bk,
                const float* __restrict__ bv, const float* __restrict__ bsk,
                float* __restrict__ out_skip)
{
    const int wi = blockIdx.y;
    const float* bias; float* dst;
    switch (wi) {
        case 0:  bias = bq;  dst = g_q;      break;
        case 1:  bias = bk;  dst = g_k;      break;
        case 2:  bias = bv;  dst = g_v;      break;
        default: bias = bsk; dst = out_skip; break;
    }
    const int tid = threadIdx.x;
    const int w = tid >> 5, lane = tid & 31;
    const int wm = w & 3, wn = w >> 2;
    const int m16base = blockIdx.x * 8 + wm * 2;

    const uint4* Ah = (const uint4*)g_xA;
    const uint4* Al = (const uint4*)g_xB;
    const uint2* Bh = (const uint2*)g_wA[wi];
    const uint2* Bl = (const uint2*)g_wB[wi];

    float acc[2][8][4];
    #pragma unroll
    for (int mt = 0; mt < 2; mt++)
        #pragma unroll
        for (int nt = 0; nt < 8; nt++)
            #pragma unroll
            for (int j = 0; j < 4; j++) acc[mt][nt][j] = 0.f;

    #pragma unroll
    for (int kk = 0; kk < 8; kk++) {
        unsigned ah[2][4], al[2][4];
        #pragma unroll
        for (int mt = 0; mt < 2; mt++) {
            size_t fi = ((size_t)(m16base + mt) * 8 + kk) * 32 + lane;
            *(uint4*)ah[mt] = Ah[fi];
            *(uint4*)al[mt] = Al[fi];
        }
        unsigned bh[8][2], bl[8][2];
        #pragma unroll
        for (int nt = 0; nt < 8; nt++) {
            int fi = (kk * 16 + wn * 8 + nt) * 32 + lane;
            *(uint2*)bh[nt] = Bh[fi];
            *(uint2*)bl[nt] = Bl[fi];
        }
        #pragma unroll
        for (int mt = 0; mt < 2; mt++)
            #pragma unroll
            for (int nt = 0; nt < 8; nt++) {
                mma16816(acc[mt][nt], ah[mt], bh[nt]);
                mma16816(acc[mt][nt], ah[mt], bl[nt]);
                mma16816(acc[mt][nt], al[mt], bh[nt]);
            }
    }

    const int gid = lane >> 2, tig = lane & 3;
    #pragma unroll
    for (int mt = 0; mt < 2; mt++) {
        int rlo = (m16base + mt) * 16 + gid;
        #pragma unroll
        for (int nt = 0; nt < 8; nt++) {
            int col = wn * 64 + nt * 8 + tig * 2;
            float b0 = __ldg(bias + col);
            float b1 = __ldg(bias + col + 1);
            if (rlo < NN)
                *(float2*)(dst + (size_t)rlo * 128 + col) =
                    make_float2(acc[mt][nt][0] + b0, acc[mt][nt][1] + b1);
            if (rlo + 8 < NN)
                *(float2*)(dst + (size_t)(rlo + 8) * 128 + col) =
                    make_float2(acc[mt][nt][2] + b0, acc[mt][nt][3] + b1);
        }
    }
}

// ---------------- kernel 2: qe = We_h^T q   [N,2,128] ----------------
#define QE_SMEM ((64 * 68 + 64 * 132) * 4)
__global__ void __launch_bounds__(256)
qe_kernel(const float* __restrict__ We)
{
    extern __shared__ float sm[];
    float* As = sm;
    float* Bs = sm + 64 * 68;

    const int tid = threadIdx.x;
    const int h = blockIdx.y;
    const int row0 = blockIdx.x * 64;

    #pragma unroll
    for (int i = 0; i < 32; i++) {
        int idx = i * 256 + tid;
        int j = idx >> 6, c = idx & 63;
        Bs[c * 132 + j] = We[j * 128 + h * 64 + c];
    }
    #pragma unroll
    for (int i = 0; i < 4; i++) {
        int idx4 = i * 256 + tid;
        int r = idx4 >> 4, c4 = idx4 & 15;
        float4 v = make_float4(0.f, 0.f, 0.f, 0.f);
        if (row0 + r < NN) v = *(const float4*)(g_q + (size_t)(row0 + r) * 128 + h * 64 + c4 * 4);
        *(float4*)(As + r * 68 + c4 * 4) = v;
    }
    __syncthreads();

    const int tx = tid & 15;
    const int ty = tid >> 4;
    const int j0 = tx * 8;
    const int r0 = ty * 4;

    float acc[4][8];
    #pragma unroll
    for (int i = 0; i < 4; i++)
        #pragma unroll
        for (int j = 0; j < 8; j++) acc[i][j] = 0.f;

    #pragma unroll 4
    for (int c = 0; c < 64; c++) {
        float4 b0 = *(const float4*)(Bs + c * 132 + j0);
        float4 b1 = *(const float4*)(Bs + c * 132 + j0 + 4);
        #pragma unroll
        for (int i = 0; i < 4; i++) {
            float a = As[(r0 + i) * 68 + c];
            acc[i][0] += a * b0.x; acc[i][1] += a * b0.y;
            acc[i][2] += a * b0.z; acc[i][3] += a * b0.w;
            acc[i][4] += a * b1.x; acc[i][5] += a * b1.y;
            acc[i][6] += a * b1.z; acc[i][7] += a * b1.w;
        }
    }

    #pragma unroll
    for (int i = 0; i < 4; i++) {
        int r = row0 + r0 + i;
        if (r < NN) {
            float* dstp = g_qe + (size_t)r * 256 + h * 128 + j0;
            *(float4*)(dstp)     = make_float4(acc[i][0], acc[i][1], acc[i][2], acc[i][3]);
            *(float4*)(dstp + 4) = make_float4(acc[i][4], acc[i][5], acc[i][6], acc[i][7]);
        }
    }
}

// ---------------- kernel 3: per-edge time-enc + alpha (+ dst histogram) ----------------
__global__ void __launch_bounds__(256)
edge_kernel(const float* __restrict__ last_update,
            const int* __restrict__ eidx,
            const float* __restrict__ t,
            const float* __restrict__ msg,
            const float* __restrict__ wt,
            const float* __restrict__ bt)
{
    __shared__ float sts[32 * 68];
    __shared__ float swt[64], sbt[64];

    const int tid = threadIdx.x;
    if (tid < 64) { swt[tid] = wt[tid]; sbt[tid] = bt[tid]; }
    __syncthreads();

    const int w = tid >> 5, lane = tid & 31;
    const int g = lane >> 3, l = lane & 7;
    const int le = w * 4 + g;
    const int e = blockIdx.x * 32 + le;

    const int s = eidx[e];
    const int d = eidx[EE + e];
    const float rt = last_update[s] - t[e];

    if (l == 0) atomicAdd(&g_cnt[d], 1);

    float tsv[8];
    #pragma unroll
    for (int u = 0; u < 8; u++) {
        int c = l * 8 + u;
        tsv[u] = cos_fast(fmaf(rt, swt[c], sbt[c]));
    }
    *(float4*)(sts + le * 68 + l * 8)     = make_float4(tsv[0], tsv[1], tsv[2], tsv[3]);
    *(float4*)(sts + le * 68 + l * 8 + 4) = make_float4(tsv[4], tsv[5], tsv[6], tsv[7]);
    __syncwarp();

    const float4* q4 = (const float4*)g_q;
    const float4* k4 = (const float4*)g_k;
    const float4* msg4 = (const float4*)msg;
    const float4* qe4 = (const float4*)g_qe;

    size_t qb = (size_t)d * 32, kb = (size_t)s * 32;
    float ph0 = dot4(q4[qb + l], k4[kb + l]) + dot4(q4[qb + l + 8], k4[kb + l + 8]);
    float ph1 = dot4(q4[qb + l + 16], k4[kb + l + 16]) + dot4(q4[qb + l + 24], k4[kb + l + 24]);

    float4 tsA = *(const float4*)(sts + le * 68 + l * 4);
    float4 tsB = *(const float4*)(sts + le * 68 + l * 4 + 32);
    float4 m0 = msg4[(size_t)e * 16 + l];
    float4 m1 = msg4[(size_t)e * 16 + l + 8];
    size_t qeb = (size_t)d * 64;
    ph0 += dot4(qe4[qeb + l], tsA) + dot4(qe4[qeb + l + 8], tsB)
         + dot4(qe4[qeb + l + 16], m0) + dot4(qe4[qeb + l + 24], m1);
    ph1 += dot4(qe4[qeb + 32 + l], tsA) + dot4(qe4[qeb + 32 + l + 8], tsB)
         + dot4(qe4[qeb + 32 + l + 16], m0) + dot4(qe4[qeb + 32 + l + 24], m1);

    #pragma unroll
    for (int o = 4; o; o >>= 1) {
        ph0 += __shfl_xor_sync(0xffffffffu, ph0, o);
        ph1 += __shfl_xor_sync(0xffffffffu, ph1, o);
    }
    if (l == 0)
        *(float2*)(g_alpha + (size_t)e * 2) = make_float2(ph0 * 0.125f, ph1 * 0.125f);
}

// ---------------- kernel 4: exclusive prefix scan (single block) ----------------
__global__ void __launch_bounds__(1024)
scan_kernel()
{
    __shared__ int warpsum[32];
    __shared__ int carry;
    const int tid = threadIdx.x;
    const int wid = tid >> 5, lane = tid & 31;
    if (tid == 0) carry = 0;
    __syncthreads();

    for (int base = 0; base < NN; base += 1024) {
        int i = base + tid;
        int v = (i < NN) ? g_cnt[i] : 0;
        int x = v;
        #pragma unroll
        for (int o = 1; o < 32; o <<= 1) {
            int y = __shfl_up_sync(0xffffffffu, x, o);
            if (lane >= o) x += y;
        }
        if (lane == 31) warpsum[wid] = x;
        __syncthreads();
        if (tid < 32) {
            int s_ = warpsum[tid];
            #pragma unroll
            for (int o = 1; o < 32; o <<= 1) {
                int y = __shfl_up_sync(0xffffffffu, s_, o);
                if (tid >= o) s_ += y;
            }
            warpsum[tid] = s_;
        }
        __syncthreads();
        int incl = x + (wid > 0 ? warpsum[wid - 1] : 0) + carry;
        if (i < NN) {
            g_off[i] = incl - v;
            g_cur[i] = incl - v;
        }
        __syncthreads();
        if (tid == 0) carry += warpsum[31];
        __syncthreads();
    }
    if (threadIdx.x == 0) g_off[NN] = carry;
}

// ---------------- kernel 5: scatter edges into dst-sorted order ----------------
__global__ void scatter_kernel(const int* __restrict__ eidx) {
    int e = blockIdx.x * blockDim.x + threadIdx.x;
    if (e >= EE) return;
    int d = eidx[EE + e];
    int pos = atomicAdd(&g_cur[d], 1);
    g_eord[pos] = e;
}

// ---------------- kernel 6: per-dst softmax + aggregation (no atomics) ----------------
__global__ void __launch_bounds__(256)
agg_kernel(const int* __restrict__ eidx, const float* __restrict__ msg,
           const float* __restrict__ last_update, const float* __restrict__ t,
           const float* __restrict__ wt, const float* __restrict__ bt,
           float* __restrict__ out)
{
    __shared__ float swt[64], sbt[64];
    const int tid = threadIdx.x;
    if (tid < 64) { swt[tid] = wt[tid]; sbt[tid] = bt[tid]; }
    __syncthreads();

    const int d = blockIdx.x * 8 + (tid >> 5);
    const int lane = tid & 31;

    const int beg = g_off[d];
    const int n = g_off[d + 1] - beg;

    float aO[4]  = {0.f, 0.f, 0.f, 0.f};
    float aA0[4] = {0.f, 0.f, 0.f, 0.f};
    float aA1[4] = {0.f, 0.f, 0.f, 0.f};

    if (n > 0) {
        float m0 = -CUDART_INF_F, m1 = -CUDART_INF_F;
        for (int j = lane; j < n; j += 32) {
            int e = g_eord[beg + j];
            float2 al = *(const float2*)(g_alpha + (size_t)e * 2);
            m0 = fmaxf(m0, al.x);
            m1 = fmaxf(m1, al.y);
        }
        #pragma unroll
        for (int o = 16; o; o >>= 1) {
            m0 = fmaxf(m0, __shfl_xor_sync(0xffffffffu, m0, o));
            m1 = fmaxf(m1, __shfl_xor_sync(0xffffffffu, m1, o));
        }
        float s0 = 0.f, s1 = 0.f;
        for (int j = lane; j < n; j += 32) {
            int e = g_eord[beg + j];
            float2 al = *(const float2*)(g_alpha + (size_t)e * 2);
            s0 += expf(al.x - m0);
            s1 += expf(al.y - m1);
        }
        #pragma unroll
        for (int o = 16; o; o >>= 1) {
            s0 += __shfl_xor_sync(0xffffffffu, s0, o);
            s1 += __shfl_xor_sync(0xffffffffu, s1, o);
        }
        const float inv0 = 1.f / (s0 + 1e-16f);
        const float inv1 = 1.f / (s1 + 1e-16f);

        for (int j = 0; j < n; j++) {
            int e = g_eord[beg + j];
            int s = eidx[e];
            float2 al = *(const float2*)(g_alpha + (size_t)e * 2);
            float a0 = expf(al.x - m0) * inv0;
            float a1 = expf(al.y - m1) * inv1;

            float4 v4 = ((const float4*)g_v)[(size_t)s * 32 + lane];
            float ah = (lane < 16) ? a0 : a1;
            aO[0] += ah * v4.x; aO[1] += ah * v4.y;
            aO[2] += ah * v4.z; aO[3] += ah * v4.w;

            float4 ea;
            if (lane < 16) {
                float rt = last_update[s] - t[e];
                int c = lane * 4;
                ea.x = cos_fast(fmaf(rt, swt[c + 0], sbt[c + 0]));
                ea.y = cos_fast(fmaf(rt, swt[c + 1], sbt[c + 1]));
                ea.z = cos_fast(fmaf(rt, swt[c + 2], sbt[c + 2]));
                ea.w = cos_fast(fmaf(rt, swt[c + 3], sbt[c + 3]));
            } else {
                ea = ((const float4*)msg)[(size_t)e * 16 + (lane - 16)];
            }
            aA0[0] += a0 * ea.x; aA0[1] += a0 * ea.y;
            aA0[2] += a0 * ea.z; aA0[3] += a0 * ea.w;
            aA1[0] += a1 * ea.x; aA1[1] += a1 * ea.y;
            aA1[2] += a1 * ea.z; aA1[3] += a1 * ea.w;
        }

        float4* op = (float4*)out + (size_t)d * 32 + lane;
        float4 cur = *op;
        cur.x += aO[0]; cur.y += aO[1]; cur.z += aO[2]; cur.w += aO[3];
        *op = cur;
    }

    ((float4*)g_accA)[(size_t)d * 64 + lane]      = make_float4(aA0[0], aA0[1], aA0[2], aA0[3]);
    ((float4*)g_accA)[(size_t)d * 64 + 32 + lane] = make_float4(aA1[0], aA1[1], aA1[2], aA1[3]);
}

// ---------------- kernel 7: epilogue  out += accA_h @ We_h ----------------
#define EPI_SMEM ((64 * 132 + 128 * 68) * 4)
__global__ void __launch_bounds__(256)
epi_kernel(const float* __restrict__ We, float* __restrict__ out)
{
    extern __shared__ float sm[];
    float* As = sm;
    float* Bs = sm + 64 * 132;

    const int tid = threadIdx.x;
    const int h = blockIdx.y;
    const int row0 = blockIdx.x * 64;

    #pragma unroll
    for (int i = 0; i < 32; i++) {
        int idx = i * 256 + tid;
        int dd = idx >> 6, c = idx & 63;
        Bs[dd * 68 + c] = We[dd * 128 + h * 64 + c];
    }
    #pragma unroll
    for (int i = 0; i < 8; i++) {
        int idx4 = i * 256 + tid;
        int r = idx4 >> 5, k4 = idx4 & 31;
        float4 v = make_float4(0.f, 0.f, 0.f, 0.f);
        if (row0 + r < NN) v = *(const float4*)(g_accA + (size_t)(row0 + r) * 256 + h * 128 + k4 * 4);
        *(float4*)(As + r * 132 + k4 * 4) = v;
    }
    __syncthreads();

    const int tx = tid & 15;
    const int ty = tid >> 4;
    const int c0 = tx * 4;
    const int r0 = ty * 4;

    float acc[4][4];
    #pragma unroll
    for (int i = 0; i < 4; i++)
        #pragma unroll
        for (int j = 0; j < 4; j++) acc[i][j] = 0.f;

    #pragma unroll 4
    for (int k = 0; k < 128; k++) {
        float4 b = *(const float4*)(Bs + k * 68 + c0);
        #pragma unroll
        for (int i = 0; i < 4; i++) {
            float a = As[(r0 + i) * 132 + k];
            acc[i][0] += a * b.x; acc[i][1] += a * b.y;
            acc[i][2] += a * b.z; acc[i][3] += a * b.w;
        }
    }

    #pragma unroll
    for (int i = 0; i < 4; i++) {
        int r = row0 + r0 + i;
        if (r < NN) {
            float* p = out + (size_t)r * 128 + h * 64 + c0;
            float4 cur = *(float4*)p;
            cur.x += acc[i][0]; cur.y += acc[i][1];
            cur.z += acc[i][2]; cur.w += acc[i][3];
            *(float4*)p = cur;
        }
    }
}

// ---------------- launch ----------------
extern "C" void kernel_launch(void* const* d_in, const int* in_sizes, int n_in,
                              void* d_out, int out_size) {
    const float* x    = (const float*)d_in[0];
    const float* lu   = (const float*)d_in[1];
    const int*   eidx = (const int*)d_in[2];
    const float* t    = (const float*)d_in[3];
    const float* msg  = (const float*)d_in[4];
    const float* wt   = (const float*)d_in[5];
    const float* bt   = (const float*)d_in[6];
    const float* Wq   = (const float*)d_in[7];
    const float* bq   = (const float*)d_in[8];
    const float* Wk   = (const float*)d_in[9];
    const float* bk   = (const float*)d_in[10];
    const float* Wv   = (const float*)d_in[11];
    const float* bv   = (const float*)d_in[12];
    const float* We   = (const float*)d_in[13];
    const float* Wsk  = (const float*)d_in[14];
    const float* bsk  = (const float*)d_in[15];
    float* out = (float*)d_out;

    cudaFuncSetAttribute(qe_kernel,  cudaFuncAttributeMaxDynamicSharedMemorySize, QE_SMEM);
    cudaFuncSetAttribute(epi_kernel, cudaFuncAttributeMaxDynamicSharedMemorySize, EPI_SMEM);

    zero_cnt_kernel<<<(NN + 255) / 256, 256>>>();
    convx_kernel<<<NM16_PAD, 256>>>(x);
    convw_kernel<<<(4 * 8192 + 255) / 256, 256>>>(Wq, Wk, Wv, Wsk);
    node_mma_kernel<<<dim3(NM16_PAD / 8, 4), 256>>>(bq, bk, bv, bsk, out);
    qe_kernel<<<dim3((NN + 63) / 64, 2), 256, QE_SMEM>>>(We);
    edge_kernel<<<EE / 32, 256>>>(lu, eidx, t, msg, wt, bt);
    scan_kernel<<<1, 1024>>>();
    scatter_kernel<<<(EE + 255) / 256, 256>>>(eidx);
    agg_kernel<<<(NN + 7) / 8, 256>>>(eidx, msg, lu, t, wt, bt, out);
    epi_kernel<<<dim3((NN + 63) / 64, 2), 256, EPI_SMEM>>>(We, out);
}